// round 1
// baseline (speedup 1.0000x reference)
#include <cuda_runtime.h>

#define E_EDGES 131072
#define INS 128
#define OUTS 128
#define NH 8
#define DK 16
#define NT 4
#define NET 8
#define ML 240
#define TILE 128
#define MAXBLK (E_EDGES / TILE + NT)   /* 1028 */
#define EPAD (MAXBLK * TILE)
#define PADW 129

// ---------------- device scratch (no runtime allocation allowed) ----------------
__device__ int   g_perm[EPAD];
__device__ int   g_counts[NT];
__device__ int   g_cursor[NT];
__device__ int   g_seg_start[NT + 1];   // in blocks
__device__ int   g_base_slot[NT];       // in slots
__device__ float g_rte[ML * INS];
__device__ float g_KWT[NT * INS * OUTS]; // [t][i][o]  (transposed K_W)
__device__ float g_VWT[NT * INS * OUTS]; // [t][i][o]

// ---------------- setup kernels ----------------
__global__ void k_init() {
    int stride = gridDim.x * blockDim.x;
    for (int i = blockIdx.x * blockDim.x + threadIdx.x; i < EPAD; i += stride)
        g_perm[i] = -1;
    if (blockIdx.x == 0 && threadIdx.x < NT) {
        g_counts[threadIdx.x] = 0;
        g_cursor[threadIdx.x] = 0;
    }
}

__global__ void k_hist(const int* __restrict__ tau) {
    __shared__ int sc[NT];
    if (threadIdx.x < NT) sc[threadIdx.x] = 0;
    __syncthreads();
    int stride = gridDim.x * blockDim.x;
    for (int i = blockIdx.x * blockDim.x + threadIdx.x; i < E_EDGES; i += stride)
        atomicAdd(&sc[tau[i]], 1);
    __syncthreads();
    if (threadIdx.x < NT) atomicAdd(&g_counts[threadIdx.x], sc[threadIdx.x]);
}

__global__ void k_offsets() {
    int blk = 0;
    for (int t = 0; t < NT; t++) {
        g_seg_start[t] = blk;
        g_base_slot[t] = blk * TILE;
        blk += (g_counts[t] + TILE - 1) / TILE;
    }
    g_seg_start[NT] = blk;
}

__global__ void k_scatter(const int* __restrict__ tau) {
    int stride = gridDim.x * blockDim.x;
    for (int i = blockIdx.x * blockDim.x + threadIdx.x; i < E_EDGES; i += stride) {
        int t = tau[i];
        unsigned act = __activemask();
        unsigned m = __match_any_sync(act, t);
        int lane = threadIdx.x & 31;
        int leader = __ffs(m) - 1;
        int rank = __popc(m & ((1u << lane) - 1u));
        int base = 0;
        if (lane == leader) base = atomicAdd(&g_cursor[t], __popc(m));
        base = __shfl_sync(m, base, leader);
        g_perm[g_base_slot[t] + base + rank] = i;
    }
}

// rte[d][o] = lin_b[o] + sum_i emb[d][i] * lin_W[o][i]
__global__ void k_rte(const float* __restrict__ emb,
                      const float* __restrict__ linW,
                      const float* __restrict__ linb) {
    __shared__ float se[INS];
    int d = blockIdx.x, o = threadIdx.x;
    se[o] = emb[d * INS + o];
    __syncthreads();
    float acc = linb[o];
    const float* w = linW + o * INS;
#pragma unroll 8
    for (int i = 0; i < INS; i++) acc += se[i] * w[i];
    g_rte[d * INS + o] = acc;
}

// transpose K_W/V_W [t][o][i] -> [t][i][o] (one-time, tiny)
__global__ void k_transpose(const float* __restrict__ K_W,
                            const float* __restrict__ V_W) {
    __shared__ float tile[32][33];
    int which = blockIdx.z & 1;
    int t = blockIdx.z >> 1;
    const float* src = (which ? V_W : K_W) + t * INS * OUTS;
    float* dst = (which ? g_VWT : g_KWT) + t * INS * OUTS;
    int i0 = blockIdx.x * 32;
    int o0 = blockIdx.y * 32;
    for (int j = threadIdx.y; j < 32; j += 8)
        tile[j][threadIdx.x] = src[(o0 + j) * INS + i0 + threadIdx.x];
    __syncthreads();
    for (int j = threadIdx.y; j < 32; j += 8)
        dst[(i0 + j) * OUTS + o0 + threadIdx.x] = tile[threadIdx.x][j];
}

// ---------------- main kernel ----------------
__device__ __forceinline__ void gemm_128(const float* __restrict__ sh_hh,
                                         const float* __restrict__ sh_wt,
                                         float* __restrict__ sh_rs,
                                         const float* __restrict__ bias,
                                         int ty, int tx) {
    int r0 = ty << 3;
    float acc[8][8];
#pragma unroll
    for (int i = 0; i < 8; i++)
#pragma unroll
        for (int j = 0; j < 8; j++) acc[i][j] = 0.f;

#pragma unroll 2
    for (int k = 0; k < INS; k++) {
        float a[8], bb[8];
#pragma unroll
        for (int i = 0; i < 8; i++) a[i] = sh_hh[(r0 + i) * PADW + k];
#pragma unroll
        for (int j = 0; j < 8; j++) bb[j] = sh_wt[k * PADW + tx + 16 * j];
#pragma unroll
        for (int i = 0; i < 8; i++)
#pragma unroll
            for (int j = 0; j < 8; j++) acc[i][j] += a[i] * bb[j];
    }
#pragma unroll
    for (int j = 0; j < 8; j++) {
        int c = tx + 16 * j;
        float bs = bias[c];
#pragma unroll
        for (int i = 0; i < 8; i++)
            sh_rs[(r0 + i) * PADW + c] = acc[i][j] + bs;
    }
}

__global__ __launch_bounds__(256, 1) void k_main(
    const int* __restrict__ etype, const float* __restrict__ h_s,
    const float* __restrict__ Q_t, const int* __restrict__ dtv,
    const float* __restrict__ K_b, const float* __restrict__ V_b,
    const float* __restrict__ Watt, const float* __restrict__ Wmsg,
    const float* __restrict__ mu, float* __restrict__ out) {
    extern __shared__ float dyn[];
    float* sh_hh = dyn;                    // [128][129] row-major (edge, in)
    float* sh_wt = dyn + TILE * PADW;      // [128][129] (k=in, o=out)
    float* sh_rs = dyn + 2 * TILE * PADW;  // [128][129] (edge, out)
    __shared__ int   sm_perm[TILE];
    __shared__ int   sm_et[TILE];
    __shared__ int   sm_dt[TILE];
    __shared__ float sWattT[NET * DK * DK]; // [et][k][o]
    __shared__ float sWmsgT[NET * DK * DK]; // [et][k][o]
    __shared__ float sMu[NET * NH];

    int tid = threadIdx.x;
    int b = blockIdx.x;
    if (b >= g_seg_start[NT]) return;

    int t = 0;
#pragma unroll
    for (int q = 1; q < NT; q++)
        if (b >= g_seg_start[q]) t = q;
    int slot0 = g_base_slot[t] + (b - g_seg_start[t]) * TILE;

    if (tid < TILE) {
        int p = g_perm[slot0 + tid];
        sm_perm[tid] = p;
        int pe = (p < 0) ? 0 : p;
        sm_et[tid] = etype[pe];
        sm_dt[tid] = dtv[pe];
    }
    for (int idx = tid; idx < NET * DK * DK; idx += 256) {
        int et = idx >> 8, rem = idx & 255, o = rem >> 4, k = rem & 15;
        int dstIdx = (et << 8) + (k << 4) + o;
        sWattT[dstIdx] = Watt[idx];
        sWmsgT[dstIdx] = Wmsg[idx];
    }
    if (tid < NET * NH) sMu[tid] = mu[tid];
    __syncthreads();

    // build h_hat tile + stage transposed K weights
    for (int idx = tid; idx < TILE * INS; idx += 256) {
        int r = idx >> 7, i = idx & 127;
        int p = sm_perm[r];
        float v = 0.f;
        if (p >= 0) v = h_s[p * INS + i] + g_rte[sm_dt[r] * INS + i];
        sh_hh[r * PADW + i] = v;
    }
    {
        const float* wt = g_KWT + t * INS * OUTS;
        for (int idx = tid; idx < INS * OUTS; idx += 256) {
            int i = idx >> 7, o = idx & 127;
            sh_wt[i * PADW + o] = wt[idx];
        }
    }
    __syncthreads();

    int ty = tid >> 4, tx = tid & 15;
    gemm_128(sh_hh, sh_wt, sh_rs, K_b + t * OUTS, ty, tx);   // sh_rs = K_s
    __syncthreads();

    // att epilogue: attk[e,h,o] = sum_k K_s[e,h,k]*Watt[et,o,k]; att = sum_o Q*attk
    for (int idx = tid; idx < TILE * OUTS; idx += 256) {
        int r = idx >> 7, c = idx & 127;
        int p = sm_perm[r];           // uniform across warp (32 c per warp, 128 c per r)
        if (p >= 0) {
            int h = c >> 4, o = c & 15;
            int et = sm_et[r];
            const float* wrow = &sWattT[(et << 8) + o];
            const float* krow = &sh_rs[r * PADW + (h << 4)];
            float v = 0.f;
#pragma unroll
            for (int k = 0; k < DK; k++) v += krow[k] * wrow[k << 4];
            v *= Q_t[p * OUTS + c];
#pragma unroll
            for (int off = 8; off; off >>= 1)
                v += __shfl_down_sync(0xffffffffu, v, off, 16);
            if (o == 0) out[p * NH + h] = v * sMu[et * NH + h] * 0.25f;
        }
    }
    // stage transposed V weights (sh_wt free after GEMM-K; sync above covers)
    {
        const float* wt = g_VWT + t * INS * OUTS;
        for (int idx = tid; idx < INS * OUTS; idx += 256) {
            int i = idx >> 7, o = idx & 127;
            sh_wt[i * PADW + o] = wt[idx];
        }
    }
    __syncthreads();

    gemm_128(sh_hh, sh_wt, sh_rs, V_b + t * OUTS, ty, tx);   // sh_rs = V_s
    __syncthreads();

    // M epilogue: M[e,h,o] = sum_k V_s[e,h,k]*Wmsg[et,o,k]
    for (int idx = tid; idx < TILE * OUTS; idx += 256) {
        int r = idx >> 7, c = idx & 127;
        int p = sm_perm[r];
        if (p >= 0) {
            int h = c >> 4, o = c & 15;
            int et = sm_et[r];
            const float* wrow = &sWmsgT[(et << 8) + o];
            const float* vrow = &sh_rs[r * PADW + (h << 4)];
            float v = 0.f;
#pragma unroll
            for (int k = 0; k < DK; k++) v += vrow[k] * wrow[k << 4];
            out[(size_t)E_EDGES * NH + (size_t)p * OUTS + c] = v;
        }
    }
}

// ---------------- launch ----------------
extern "C" void kernel_launch(void* const* d_in, const int* in_sizes, int n_in,
                              void* d_out, int out_size) {
    const int*   etype = (const int*)d_in[0];
    const int*   tau   = (const int*)d_in[1];
    const float* h_s   = (const float*)d_in[2];
    const float* Q_t   = (const float*)d_in[3];
    const int*   dtv   = (const int*)d_in[4];
    const float* emb   = (const float*)d_in[5];
    const float* linW  = (const float*)d_in[6];
    const float* linb  = (const float*)d_in[7];
    const float* K_W   = (const float*)d_in[8];
    const float* K_b   = (const float*)d_in[9];
    const float* V_W   = (const float*)d_in[10];
    const float* V_b   = (const float*)d_in[11];
    const float* Watt  = (const float*)d_in[12];
    const float* Wmsg  = (const float*)d_in[13];
    const float* mu    = (const float*)d_in[14];
    float* out = (float*)d_out;

    size_t dynsmem = (size_t)3 * TILE * PADW * sizeof(float);  // ~193.5 KB
    cudaFuncSetAttribute(k_main, cudaFuncAttributeMaxDynamicSharedMemorySize,
                         (int)dynsmem);

    k_init<<<256, 256>>>();
    k_hist<<<256, 256>>>(tau);
    k_offsets<<<1, 1>>>();
    k_scatter<<<256, 256>>>(tau);
    k_rte<<<ML, INS>>>(emb, linW, linb);
    k_transpose<<<dim3(4, 4, 2 * NT), dim3(32, 8)>>>(K_W, V_W);
    k_main<<<MAXBLK, 256, dynsmem>>>(etype, h_s, Q_t, dtv, K_b, V_b,
                                     Watt, Wmsg, mu, out);
}

// round 3
// speedup vs baseline: 3.7282x; 3.7282x over previous
#include <cuda_runtime.h>
#include <cuda_bf16.h>
#include <cstdint>

#define E_EDGES 131072
#define INS 128
#define OUTS 128
#define NH 8
#define DK 16
#define NG 32          /* tau(4) x etype(8) combined groups */
#define ML 240
#define TILE 128
#define MAXBLK (E_EDGES / TILE + NG)   /* 1056 */
#define EPAD (MAXBLK * TILE)
#define STR 136        /* bf16 elements per padded smem row (272 B) */

// ---------------- device scratch ----------------
__device__ int   g_perm[EPAD];
__device__ int   g_counts[NG];
__device__ int   g_cursor[NG];
__device__ int   g_base_slot[NG];
__device__ int   g_blk_group[MAXBLK];
__device__ float g_rte[ML * INS];
// combined weights [g][n][k] row-major bf16, hi/lo split
__device__ __nv_bfloat16 g_Batt_hi[NG * 16384];
__device__ __nv_bfloat16 g_Batt_lo[NG * 16384];
__device__ __nv_bfloat16 g_Bmsg_hi[NG * 16384];
__device__ __nv_bfloat16 g_Bmsg_lo[NG * 16384];
__device__ float g_bias_att[NG * OUTS];
__device__ float g_bias_msg[NG * OUTS];

// ---------------- helpers ----------------
__device__ __forceinline__ uint32_t smem_u32(const void* p) {
    uint32_t a;
    asm("{ .reg .u64 t; cvta.to.shared.u64 t, %1; cvt.u32.u64 %0, t; }"
        : "=r"(a) : "l"(p));
    return a;
}
__device__ __forceinline__ void ldmx4(uint32_t* r, uint32_t addr) {
    asm volatile("ldmatrix.sync.aligned.m8n8.x4.shared.b16 {%0,%1,%2,%3}, [%4];"
                 : "=r"(r[0]), "=r"(r[1]), "=r"(r[2]), "=r"(r[3]) : "r"(addr));
}
__device__ __forceinline__ void ldmx2(uint32_t* r, uint32_t addr) {
    asm volatile("ldmatrix.sync.aligned.m8n8.x2.shared.b16 {%0,%1}, [%2];"
                 : "=r"(r[0]), "=r"(r[1]) : "r"(addr));
}
__device__ __forceinline__ void mma16816(float* c, const uint32_t* a, const uint32_t* b) {
    asm volatile(
        "mma.sync.aligned.m16n8k16.row.col.f32.bf16.bf16.f32 "
        "{%0,%1,%2,%3}, {%4,%5,%6,%7}, {%8,%9}, {%0,%1,%2,%3};"
        : "+f"(c[0]), "+f"(c[1]), "+f"(c[2]), "+f"(c[3])
        : "r"(a[0]), "r"(a[1]), "r"(a[2]), "r"(a[3]), "r"(b[0]), "r"(b[1]));
}
__device__ __forceinline__ unsigned pack_bf16(float a, float b) {
    __nv_bfloat162 t = __floats2bfloat162_rn(a, b);
    return *reinterpret_cast<unsigned*>(&t);
}

// ---------------- setup kernels ----------------
__global__ void k_init() {
    int stride = gridDim.x * blockDim.x;
    for (int i = blockIdx.x * blockDim.x + threadIdx.x; i < EPAD; i += stride)
        g_perm[i] = -1;
    if (blockIdx.x == 0 && threadIdx.x < NG) {
        g_counts[threadIdx.x] = 0;
        g_cursor[threadIdx.x] = 0;
    }
}

__global__ void k_hist(const int* __restrict__ etype, const int* __restrict__ tau) {
    __shared__ int sc[NG];
    if (threadIdx.x < NG) sc[threadIdx.x] = 0;
    __syncthreads();
    int stride = gridDim.x * blockDim.x;
    for (int i = blockIdx.x * blockDim.x + threadIdx.x; i < E_EDGES; i += stride)
        atomicAdd(&sc[tau[i] * 8 + etype[i]], 1);
    __syncthreads();
    if (threadIdx.x < NG) atomicAdd(&g_counts[threadIdx.x], sc[threadIdx.x]);
}

__global__ void k_offsets() {
    int blk = 0;
    for (int g = 0; g < NG; g++) {
        g_base_slot[g] = blk * TILE;
        int nb = (g_counts[g] + TILE - 1) / TILE;
        for (int b = 0; b < nb; b++) g_blk_group[blk + b] = g;
        blk += nb;
    }
    for (int b = blk; b < MAXBLK; b++) g_blk_group[b] = -1;
}

__global__ void k_scatter(const int* __restrict__ etype, const int* __restrict__ tau) {
    int stride = gridDim.x * blockDim.x;
    for (int i = blockIdx.x * blockDim.x + threadIdx.x; i < E_EDGES; i += stride) {
        int g = tau[i] * 8 + etype[i];
        unsigned act = __activemask();
        unsigned m = __match_any_sync(act, g);
        int lane = threadIdx.x & 31;
        int leader = __ffs(m) - 1;
        int rank = __popc(m & ((1u << lane) - 1u));
        int base = 0;
        if (lane == leader) base = atomicAdd(&g_cursor[g], __popc(m));
        base = __shfl_sync(m, base, leader);
        g_perm[g_base_slot[g] + base + rank] = i;
    }
}

__global__ void k_rte(const float* __restrict__ emb,
                      const float* __restrict__ linW,
                      const float* __restrict__ linb) {
    __shared__ float se[INS];
    int d = blockIdx.x, o = threadIdx.x;
    se[o] = emb[d * INS + o];
    __syncthreads();
    float acc = linb[o];
    const float* w = linW + o * INS;
#pragma unroll 8
    for (int i = 0; i < INS; i++) acc += se[i] * w[i];
    g_rte[d * INS + o] = acc;
}

// combined weights Wc[g][n=h*16+o][i] = sum_k W2[et][o][k]*W1[t][h*16+k][i], hi/lo bf16
__global__ void k_wcomb(const float* __restrict__ K_W, const float* __restrict__ K_b,
                        const float* __restrict__ V_W, const float* __restrict__ V_b,
                        const float* __restrict__ Watt, const float* __restrict__ Wmsg) {
    int n = blockIdx.x;        // 0..127
    int g = blockIdx.y;        // 0..31
    int which = blockIdx.z;    // 0 = att, 1 = msg
    int i = threadIdx.x;       // 0..127
    int t = g >> 3, et = g & 7, h = n >> 4, o = n & 15;
    const float* W2 = (which ? Wmsg : Watt) + (et * 16 + o) * 16;
    const float* W1 = (which ? V_W : K_W) + t * 16384;
    const float* b1 = (which ? V_b : K_b) + t * 128;
    float acc = 0.f, bacc = 0.f;
#pragma unroll
    for (int k = 0; k < 16; k++) {
        float w = W2[k];
        acc += w * W1[(h * 16 + k) * 128 + i];
        bacc += w * b1[h * 16 + k];
    }
    if (i == 0) (which ? g_bias_msg : g_bias_att)[g * 128 + n] = bacc;
    __nv_bfloat16 hi = __float2bfloat16(acc);
    float lof = acc - __bfloat162float(hi);
    __nv_bfloat16 lo = __float2bfloat16(lof);
    int idx = g * 16384 + n * 128 + i;
    (which ? g_Bmsg_hi : g_Batt_hi)[idx] = hi;
    (which ? g_Bmsg_lo : g_Batt_lo)[idx] = lo;
}

// ---------------- main kernel ----------------
#define SM_AHI     0
#define SM_ALO     (TILE * STR * 2)          /* 34816 */
#define SM_BATT_HI (2 * TILE * STR * 2)      /* 69632 */
#define SM_BATT_LO (3 * TILE * STR * 2)
#define SM_BMSG_HI (4 * TILE * STR * 2)
#define SM_BMSG_LO (5 * TILE * STR * 2)
#define DYN_SMEM   (6 * TILE * STR * 2)      /* 208896 */

__global__ __launch_bounds__(256, 1) void k_main(
    const float* __restrict__ h_s, const float* __restrict__ Q_t,
    const int* __restrict__ dtv, const float* __restrict__ mu,
    float* __restrict__ out) {
    extern __shared__ char dyn[];
    __shared__ int   sm_perm[TILE];
    __shared__ float sBa[OUTS];
    __shared__ float sBm[OUTS];
    __shared__ float sMu[NH];

    int b = blockIdx.x;
    int g = g_blk_group[b];
    if (g < 0) return;

    int tid = threadIdx.x;
    int lane = tid & 31;
    int w = tid >> 5;
    int wr = w >> 2, wc = w & 3;
    int R0 = wr * 64, C0 = wc * 32;

    if (tid < TILE) {
        sm_perm[tid] = g_perm[b * TILE + tid];
        sBa[tid] = g_bias_att[g * 128 + tid];
        sBm[tid] = g_bias_msg[g * 128 + tid];
    }
    if (tid < NH) sMu[tid] = mu[(g & 7) * NH + tid];

    // stage 4 weight tiles into padded smem
    {
        const uint4* srcs[4] = {
            (const uint4*)(g_Batt_hi + g * 16384), (const uint4*)(g_Batt_lo + g * 16384),
            (const uint4*)(g_Bmsg_hi + g * 16384), (const uint4*)(g_Bmsg_lo + g * 16384)};
        char* dsts[4] = {dyn + SM_BATT_HI, dyn + SM_BATT_LO,
                         dyn + SM_BMSG_HI, dyn + SM_BMSG_LO};
#pragma unroll
        for (int tIdx = 0; tIdx < 4; tIdx++) {
            const uint4* s = srcs[tIdx];
            char* d = dsts[tIdx];
            for (int idx = tid; idx < 2048; idx += 256) {
                int n = idx >> 4, kc = idx & 15;
                *(uint4*)(d + n * 272 + kc * 16) = s[idx];
            }
        }
    }
    __syncthreads();  // sm_perm ready for A staging

    // build A (hh) tile: hi/lo bf16 split. 2 threads per row.
    {
        int r = tid >> 1, half = tid & 1;
        int p = sm_perm[r];
        const float4* hs4 = (const float4*)(h_s + (size_t)(p < 0 ? 0 : p) * 128);
        int d = (p >= 0) ? dtv[p] : 0;
        const float4* rt4 = (const float4*)(g_rte + d * 128);
        char* smA_hi = dyn + SM_AHI + r * 272 + half * 128;
        char* smA_lo = dyn + SM_ALO + r * 272 + half * 128;
#pragma unroll 4
        for (int j = 0; j < 16; j++) {
            float v0 = 0.f, v1 = 0.f, v2 = 0.f, v3 = 0.f;
            if (p >= 0) {
                float4 hv = hs4[half * 16 + j];
                float4 rv = rt4[half * 16 + j];
                v0 = hv.x + rv.x; v1 = hv.y + rv.y;
                v2 = hv.z + rv.z; v3 = hv.w + rv.w;
            }
            __nv_bfloat16 h0 = __float2bfloat16(v0), h1 = __float2bfloat16(v1);
            __nv_bfloat16 h2 = __float2bfloat16(v2), h3 = __float2bfloat16(v3);
            *(unsigned*)(smA_hi + j * 8)     = pack_bf16(v0, v1);  // placeholder, fixed below
            // NOTE: pack hi parts properly:
            {
                __nv_bfloat162 t0{h0, h1}, t1{h2, h3};
                *(unsigned*)(smA_hi + j * 8)     = *reinterpret_cast<unsigned*>(&t0);
                *(unsigned*)(smA_hi + j * 8 + 4) = *reinterpret_cast<unsigned*>(&t1);
            }
            float l0 = v0 - __bfloat162float(h0), l1 = v1 - __bfloat162float(h1);
            float l2 = v2 - __bfloat162float(h2), l3 = v3 - __bfloat162float(h3);
            *(unsigned*)(smA_lo + j * 8)     = pack_bf16(l0, l1);
            *(unsigned*)(smA_lo + j * 8 + 4) = pack_bf16(l2, l3);
        }
    }
    __syncthreads();

    uint32_t sb = smem_u32(dyn);
    uint32_t aHiB = sb + SM_AHI, aLoB = sb + SM_ALO;
    // ldmatrix lane-address offsets
    uint32_t aOff = (uint32_t)((R0 + (lane & 15)) * 272 + (lane >> 4) * 16);
    uint32_t bOff = (uint32_t)((C0 + (lane & 7)) * 272 + ((lane >> 3) & 1) * 16);

    int q4 = lane & 3, rquad = lane >> 2;

#pragma unroll
    for (int phase = 0; phase < 2; phase++) {
        uint32_t bHiB = sb + (phase ? SM_BMSG_HI : SM_BATT_HI);
        uint32_t bLoB = sb + (phase ? SM_BMSG_LO : SM_BATT_LO);
        float acc[4][4][4];
#pragma unroll
        for (int mt = 0; mt < 4; mt++)
#pragma unroll
            for (int nt = 0; nt < 4; nt++)
#pragma unroll
                for (int v = 0; v < 4; v++) acc[mt][nt][v] = 0.f;

#pragma unroll
        for (int k = 0; k < 8; k++) {
            uint32_t kb = (uint32_t)(k * 32);
            uint32_t bh[4][2], bl[4][2];
#pragma unroll
            for (int nt = 0; nt < 4; nt++) {
                ldmx2(bh[nt], bHiB + bOff + nt * 8 * 272 + kb);
                ldmx2(bl[nt], bLoB + bOff + nt * 8 * 272 + kb);
            }
#pragma unroll
            for (int mt = 0; mt < 4; mt++) {
                uint32_t ah[4], al[4];
                ldmx4(ah, aHiB + aOff + mt * 16 * 272 + kb);
                ldmx4(al, aLoB + aOff + mt * 16 * 272 + kb);
#pragma unroll
                for (int nt = 0; nt < 4; nt++) {
                    mma16816(acc[mt][nt], ah, bh[nt]);
                    mma16816(acc[mt][nt], ah, bl[nt]);
                    mma16816(acc[mt][nt], al, bh[nt]);
                }
            }
        }

        if (phase == 0) {
            // attention epilogue: att[e,h] = mu[h]/4 * sum_o Q[e,h,o]*(acc+bias)
            float hsum[4][2][2];
#pragma unroll
            for (int mt = 0; mt < 4; mt++)
#pragma unroll
                for (int rf = 0; rf < 2; rf++)
#pragma unroll
                    for (int hl = 0; hl < 2; hl++) hsum[mt][rf][hl] = 0.f;
#pragma unroll
            for (int mt = 0; mt < 4; mt++) {
                int r1 = R0 + mt * 16 + rquad;
                int p1 = sm_perm[r1], p2 = sm_perm[r1 + 8];
#pragma unroll
                for (int nt = 0; nt < 4; nt++) {
                    int col = C0 + nt * 8 + q4 * 2;
                    float b0 = sBa[col], b1 = sBa[col + 1];
                    int hl = nt >> 1;
                    if (p1 >= 0) {
                        float2 q = *(const float2*)(Q_t + (size_t)p1 * 128 + col);
                        hsum[mt][0][hl] += (acc[mt][nt][0] + b0) * q.x +
                                           (acc[mt][nt][1] + b1) * q.y;
                    }
                    if (p2 >= 0) {
                        float2 q = *(const float2*)(Q_t + (size_t)p2 * 128 + col);
                        hsum[mt][1][hl] += (acc[mt][nt][2] + b0) * q.x +
                                           (acc[mt][nt][3] + b1) * q.y;
                    }
                }
            }
#pragma unroll
            for (int mt = 0; mt < 4; mt++)
#pragma unroll
                for (int rf = 0; rf < 2; rf++)
#pragma unroll
                    for (int hl = 0; hl < 2; hl++) {
                        float v = hsum[mt][rf][hl];
                        v += __shfl_xor_sync(0xffffffffu, v, 1);
                        v += __shfl_xor_sync(0xffffffffu, v, 2);
                        if (q4 == 0) {
                            int rr = R0 + mt * 16 + rf * 8 + rquad;
                            int p = sm_perm[rr];
                            if (p >= 0) {
                                int h = wc * 2 + hl;
                                out[(size_t)p * 8 + h] = v * sMu[h] * 0.25f;
                            }
                        }
                    }
        } else {
            // message epilogue
            float* mout = out + (size_t)E_EDGES * 8;
#pragma unroll
            for (int mt = 0; mt < 4; mt++) {
                int r1 = R0 + mt * 16 + rquad;
                int p1 = sm_perm[r1], p2 = sm_perm[r1 + 8];
#pragma unroll
                for (int nt = 0; nt < 4; nt++) {
                    int col = C0 + nt * 8 + q4 * 2;
                    float b0 = sBm[col], b1 = sBm[col + 1];
                    if (p1 >= 0)
                        *(float2*)(mout + (size_t)p1 * 128 + col) =
                            make_float2(acc[mt][nt][0] + b0, acc[mt][nt][1] + b1);
                    if (p2 >= 0)
                        *(float2*)(mout + (size_t)p2 * 128 + col) =
                            make_float2(acc[mt][nt][2] + b0, acc[mt][nt][3] + b1);
                }
            }
        }
    }
}

// ---------------- launch ----------------
extern "C" void kernel_launch(void* const* d_in, const int* in_sizes, int n_in,
                              void* d_out, int out_size) {
    const int*   etype = (const int*)d_in[0];
    const int*   tau   = (const int*)d_in[1];
    const float* h_s   = (const float*)d_in[2];
    const float* Q_t   = (const float*)d_in[3];
    const int*   dtv   = (const int*)d_in[4];
    const float* emb   = (const float*)d_in[5];
    const float* linW  = (const float*)d_in[6];
    const float* linb  = (const float*)d_in[7];
    const float* K_W   = (const float*)d_in[8];
    const float* K_b   = (const float*)d_in[9];
    const float* V_W   = (const float*)d_in[10];
    const float* V_b   = (const float*)d_in[11];
    const float* Watt  = (const float*)d_in[12];
    const float* Wmsg  = (const float*)d_in[13];
    const float* mu    = (const float*)d_in[14];
    float* out = (float*)d_out;

    cudaFuncSetAttribute(k_main, cudaFuncAttributeMaxDynamicSharedMemorySize, DYN_SMEM);

    k_init<<<256, 256>>>();
    k_hist<<<256, 256>>>(etype, tau);
    k_offsets<<<1, 1>>>();
    k_scatter<<<256, 256>>>(etype, tau);
    k_rte<<<ML, INS>>>(emb, linW, linb);
    k_wcomb<<<dim3(OUTS, NG, 2), INS>>>(K_W, K_b, V_W, V_b, Watt, Wmsg);
    k_main<<<MAXBLK, 256, DYN_SMEM>>>(h_s, Q_t, dtv, mu, out);
}

// round 4
// speedup vs baseline: 4.4903x; 1.2044x over previous
#include <cuda_runtime.h>
#include <cuda_bf16.h>
#include <cstdint>

#define E_EDGES 131072
#define INS 128
#define OUTS 128
#define NH 8
#define DK 16
#define NG 32          /* tau(4) x etype(8) combined groups */
#define ML 240
#define TILE 128
#define MAXBLK (E_EDGES / TILE + NG)   /* 1056 */
#define STR 136        /* bf16 elements per padded smem row (272 B) */

// ---------------- device scratch ----------------
__device__ int   g_perm[MAXBLK * TILE];
__device__ int   g_counts[NG];
__device__ int   g_cursor[NG];
__device__ int   g_blk_info[MAXBLK];   // g | (valid<<8), or -1
__device__ float g_rte[ML * INS];
// combined weights [g][n][k] row-major bf16, hi/lo split
__device__ __nv_bfloat16 g_Batt_hi[NG * 16384];
__device__ __nv_bfloat16 g_Batt_lo[NG * 16384];
__device__ __nv_bfloat16 g_Bmsg_hi[NG * 16384];
__device__ __nv_bfloat16 g_Bmsg_lo[NG * 16384];
__device__ float g_bias_att[NG * OUTS];
__device__ float g_bias_msg[NG * OUTS];

// ---------------- helpers ----------------
__device__ __forceinline__ uint32_t smem_u32(const void* p) {
    uint32_t a;
    asm("{ .reg .u64 t; cvta.to.shared.u64 t, %1; cvt.u32.u64 %0, t; }"
        : "=r"(a) : "l"(p));
    return a;
}
__device__ __forceinline__ void ldmx4(uint32_t* r, uint32_t addr) {
    asm volatile("ldmatrix.sync.aligned.m8n8.x4.shared.b16 {%0,%1,%2,%3}, [%4];"
                 : "=r"(r[0]), "=r"(r[1]), "=r"(r[2]), "=r"(r[3]) : "r"(addr));
}
__device__ __forceinline__ void ldmx2(uint32_t* r, uint32_t addr) {
    asm volatile("ldmatrix.sync.aligned.m8n8.x2.shared.b16 {%0,%1}, [%2];"
                 : "=r"(r[0]), "=r"(r[1]) : "r"(addr));
}
__device__ __forceinline__ void mma16816(float* c, const uint32_t* a, const uint32_t* b) {
    asm volatile(
        "mma.sync.aligned.m16n8k16.row.col.f32.bf16.bf16.f32 "
        "{%0,%1,%2,%3}, {%4,%5,%6,%7}, {%8,%9}, {%0,%1,%2,%3};"
        : "+f"(c[0]), "+f"(c[1]), "+f"(c[2]), "+f"(c[3])
        : "r"(a[0]), "r"(a[1]), "r"(a[2]), "r"(a[3]), "r"(b[0]), "r"(b[1]));
}
__device__ __forceinline__ unsigned pack_bf16(float a, float b) {
    __nv_bfloat162 t = __floats2bfloat162_rn(a, b);
    return *reinterpret_cast<unsigned*>(&t);
}
__device__ __forceinline__ void cp_async16(uint32_t saddr, const void* gaddr) {
    asm volatile("cp.async.cg.shared.global [%0], [%1], 16;"
                 :: "r"(saddr), "l"(gaddr));
}
__device__ __forceinline__ void cp_async_commit_wait() {
    asm volatile("cp.async.commit_group;");
    asm volatile("cp.async.wait_group 0;");
}

// ---------------- setup kernels ----------------
// RTE table + zero the group counters (block 0)
__global__ void k_rte(const float* __restrict__ emb,
                      const float* __restrict__ linW,
                      const float* __restrict__ linb) {
    __shared__ float se[INS];
    int d = blockIdx.x, o = threadIdx.x;
    if (d == 0 && o < NG) g_counts[o] = 0;
    se[o] = emb[d * INS + o];
    __syncthreads();
    float acc = linb[o];
    const float* w = linW + o * INS;
#pragma unroll 8
    for (int i = 0; i < INS; i++) acc += se[i] * w[i];
    g_rte[d * INS + o] = acc;
}

__global__ void k_hist(const int* __restrict__ etype, const int* __restrict__ tau) {
    __shared__ int sc[NG];
    if (threadIdx.x < NG) sc[threadIdx.x] = 0;
    __syncthreads();
    int i = blockIdx.x * blockDim.x + threadIdx.x;
    atomicAdd(&sc[tau[i] * 8 + etype[i]], 1);
    __syncthreads();
    if (threadIdx.x < NG && sc[threadIdx.x] > 0)
        atomicAdd(&g_counts[threadIdx.x], sc[threadIdx.x]);
}

__global__ void k_offsets() {
    __shared__ int seg[NG + 1];   // block index where each group starts
    __shared__ int cnt[NG];
    if (threadIdx.x == 0) {
        int blk = 0;
        for (int g = 0; g < NG; g++) {
            seg[g] = blk;
            int c = g_counts[g];
            cnt[g] = c;
            g_cursor[g] = blk * TILE;
            blk += (c + TILE - 1) / TILE;
        }
        seg[NG] = blk;
    }
    __syncthreads();
    int total = seg[NG];
    for (int b = threadIdx.x; b < MAXBLK; b += blockDim.x) {
        int info = -1;
        if (b < total) {
            int g = 0;
            for (int q = 1; q < NG; q++)
                if (b >= seg[q]) g = q;
            int rem = cnt[g] - (b - seg[g]) * TILE;
            int valid = rem < TILE ? rem : TILE;
            info = g | (valid << 8);
        }
        g_blk_info[b] = info;
    }
}

// block-aggregated scatter: one global atomic per group per block
__global__ void k_scatter(const int* __restrict__ etype, const int* __restrict__ tau) {
    __shared__ int lcount[NG];
    __shared__ int lbase[NG];
    int tid = threadIdx.x;
    if (tid < NG) lcount[tid] = 0;
    __syncthreads();
    int i = blockIdx.x * blockDim.x + tid;
    int g = tau[i] * 8 + etype[i];
    int rank = atomicAdd(&lcount[g], 1);
    __syncthreads();
    if (tid < NG && lcount[tid] > 0)
        lbase[tid] = atomicAdd(&g_cursor[tid], lcount[tid]);
    __syncthreads();
    g_perm[lbase[g] + rank] = i;
}

// combined weights Wc[g][n=h*16+o][i] = sum_k W2[et][o][k]*W1[t][h*16+k][i], hi/lo bf16
__global__ void k_wcomb(const float* __restrict__ K_W, const float* __restrict__ K_b,
                        const float* __restrict__ V_W, const float* __restrict__ V_b,
                        const float* __restrict__ Watt, const float* __restrict__ Wmsg) {
    int n = blockIdx.x;        // 0..127
    int g = blockIdx.y;        // 0..31
    int which = blockIdx.z;    // 0 = att, 1 = msg
    int i = threadIdx.x;       // 0..127
    int t = g >> 3, et = g & 7, h = n >> 4, o = n & 15;
    const float* W2 = (which ? Wmsg : Watt) + (et * 16 + o) * 16;
    const float* W1 = (which ? V_W : K_W) + t * 16384;
    const float* b1 = (which ? V_b : K_b) + t * 128;
    float acc = 0.f, bacc = 0.f;
#pragma unroll
    for (int k = 0; k < 16; k++) {
        float w = W2[k];
        acc += w * W1[(h * 16 + k) * 128 + i];
        bacc += w * b1[h * 16 + k];
    }
    if (i == 0) (which ? g_bias_msg : g_bias_att)[g * 128 + n] = bacc;
    __nv_bfloat16 hi = __float2bfloat16(acc);
    float lof = acc - __bfloat162float(hi);
    __nv_bfloat16 lo = __float2bfloat16(lof);
    int idx = g * 16384 + n * 128 + i;
    (which ? g_Bmsg_hi : g_Batt_hi)[idx] = hi;
    (which ? g_Bmsg_lo : g_Batt_lo)[idx] = lo;
}

// ---------------- main kernel ----------------
#define SM_AHI     0
#define SM_ALO     (TILE * STR * 2)          /* 34816 */
#define SM_BATT_HI (2 * TILE * STR * 2)      /* 69632 */
#define SM_BATT_LO (3 * TILE * STR * 2)
#define SM_BMSG_HI (4 * TILE * STR * 2)
#define SM_BMSG_LO (5 * TILE * STR * 2)
#define DYN_SMEM   (6 * TILE * STR * 2)      /* 208896 */

__global__ __launch_bounds__(256, 1) void k_main(
    const float* __restrict__ h_s, const float* __restrict__ Q_t,
    const int* __restrict__ dtv, const float* __restrict__ mu,
    float* __restrict__ out) {
    extern __shared__ char dyn[];
    __shared__ int   sm_perm[TILE];
    __shared__ float sBa[OUTS];
    __shared__ float sBm[OUTS];
    __shared__ float sMu[NH];

    int b = blockIdx.x;
    int info = g_blk_info[b];
    if (info < 0) return;
    int g = info & 31;
    int valid = info >> 8;

    int tid = threadIdx.x;
    int lane = tid & 31;
    int w = tid >> 5;
    int wr = w >> 2, wc = w & 3;
    int R0 = wr * 64, C0 = wc * 32;
    uint32_t sb = smem_u32(dyn);

    // ---- 1) kick off weight tile staging via cp.async (latency hidden by A build)
    {
        const uint4* srcs[4] = {
            (const uint4*)(g_Batt_hi + g * 16384), (const uint4*)(g_Batt_lo + g * 16384),
            (const uint4*)(g_Bmsg_hi + g * 16384), (const uint4*)(g_Bmsg_lo + g * 16384)};
        uint32_t dsts[4] = {sb + SM_BATT_HI, sb + SM_BATT_LO,
                            sb + SM_BMSG_HI, sb + SM_BMSG_LO};
#pragma unroll
        for (int tIdx = 0; tIdx < 4; tIdx++) {
            const uint4* s = srcs[tIdx];
            uint32_t d = dsts[tIdx];
#pragma unroll
            for (int it = 0; it < 8; it++) {
                int idx = tid + it * 256;
                int n = idx >> 4, kc = idx & 15;
                cp_async16(d + n * 272 + kc * 16, s + idx);
            }
        }
    }

    // ---- 2) per-block constants
    if (tid < TILE) {
        sm_perm[tid] = (tid < valid) ? g_perm[b * TILE + tid] : -1;
        sBa[tid] = g_bias_att[g * 128 + tid];
        sBm[tid] = g_bias_msg[g * 128 + tid];
    }
    if (tid < NH) sMu[tid] = mu[(g & 7) * NH + tid];

    // ---- 3) build A (hh) tile: hi/lo bf16 split, 2 threads per row
    {
        int r = tid >> 1, half = tid & 1;
        int p = (r < valid) ? g_perm[b * TILE + r] : -1;
        const float4* hs4 = (const float4*)(h_s + (size_t)(p < 0 ? 0 : p) * 128);
        int d = (p >= 0) ? dtv[p] : 0;
        const float4* rt4 = (const float4*)(g_rte + d * 128);
        char* smA_hi = dyn + SM_AHI + r * 272 + half * 128;
        char* smA_lo = dyn + SM_ALO + r * 272 + half * 128;
#pragma unroll 4
        for (int j = 0; j < 16; j++) {
            float v0 = 0.f, v1 = 0.f, v2 = 0.f, v3 = 0.f;
            if (p >= 0) {
                float4 hv = hs4[half * 16 + j];
                float4 rv = rt4[half * 16 + j];
                v0 = hv.x + rv.x; v1 = hv.y + rv.y;
                v2 = hv.z + rv.z; v3 = hv.w + rv.w;
            }
            __nv_bfloat16 h0 = __float2bfloat16(v0), h1 = __float2bfloat16(v1);
            __nv_bfloat16 h2 = __float2bfloat16(v2), h3 = __float2bfloat16(v3);
            __nv_bfloat162 t0{h0, h1}, t1{h2, h3};
            *(unsigned*)(smA_hi + j * 8)     = *reinterpret_cast<unsigned*>(&t0);
            *(unsigned*)(smA_hi + j * 8 + 4) = *reinterpret_cast<unsigned*>(&t1);
            float l0 = v0 - __bfloat162float(h0), l1 = v1 - __bfloat162float(h1);
            float l2 = v2 - __bfloat162float(h2), l3 = v3 - __bfloat162float(h3);
            *(unsigned*)(smA_lo + j * 8)     = pack_bf16(l0, l1);
            *(unsigned*)(smA_lo + j * 8 + 4) = pack_bf16(l2, l3);
        }
    }
    cp_async_commit_wait();
    __syncthreads();

    uint32_t aHiB = sb + SM_AHI, aLoB = sb + SM_ALO;
    uint32_t aOff = (uint32_t)((R0 + (lane & 15)) * 272 + (lane >> 4) * 16);
    uint32_t bOff = (uint32_t)((C0 + (lane & 7)) * 272 + ((lane >> 3) & 1) * 16);
    int q4 = lane & 3, rquad = lane >> 2;

    // row indices / perm for this thread's epilogue rows
    int pr1[4], pr2[4];
#pragma unroll
    for (int mt = 0; mt < 4; mt++) {
        pr1[mt] = sm_perm[R0 + mt * 16 + rquad];
        pr2[mt] = sm_perm[R0 + mt * 16 + rquad + 8];
    }

#pragma unroll
    for (int phase = 0; phase < 2; phase++) {
        uint32_t bHiB = sb + (phase ? SM_BMSG_HI : SM_BATT_HI);
        uint32_t bLoB = sb + (phase ? SM_BMSG_LO : SM_BATT_LO);
        float acc[4][4][4];
#pragma unroll
        for (int mt = 0; mt < 4; mt++)
#pragma unroll
            for (int nt = 0; nt < 4; nt++)
#pragma unroll
                for (int v = 0; v < 4; v++) acc[mt][nt][v] = 0.f;

        // prefetch Q for the att epilogue (phase 0 only) — hides DRAM behind MMA
        float2 qv1[4][4], qv2[4][4];
        if (phase == 0) {
#pragma unroll
            for (int mt = 0; mt < 4; mt++)
#pragma unroll
                for (int nt = 0; nt < 4; nt++) {
                    int col = C0 + nt * 8 + q4 * 2;
                    const float2* q1 = (const float2*)(Q_t +
                        (size_t)(pr1[mt] < 0 ? 0 : pr1[mt]) * 128 + col);
                    const float2* q2 = (const float2*)(Q_t +
                        (size_t)(pr2[mt] < 0 ? 0 : pr2[mt]) * 128 + col);
                    qv1[mt][nt] = __ldg(q1);
                    qv2[mt][nt] = __ldg(q2);
                }
        }

#pragma unroll
        for (int k = 0; k < 8; k++) {
            uint32_t kb = (uint32_t)(k * 32);
            uint32_t bh[4][2], bl[4][2];
#pragma unroll
            for (int nt = 0; nt < 4; nt++) {
                ldmx2(bh[nt], bHiB + bOff + nt * 8 * 272 + kb);
                ldmx2(bl[nt], bLoB + bOff + nt * 8 * 272 + kb);
            }
#pragma unroll
            for (int mt = 0; mt < 4; mt++) {
                uint32_t ah[4], al[4];
                ldmx4(ah, aHiB + aOff + mt * 16 * 272 + kb);
                ldmx4(al, aLoB + aOff + mt * 16 * 272 + kb);
#pragma unroll
                for (int nt = 0; nt < 4; nt++) {
                    mma16816(acc[mt][nt], ah, bh[nt]);
                    mma16816(acc[mt][nt], ah, bl[nt]);
                    mma16816(acc[mt][nt], al, bh[nt]);
                }
            }
        }

        if (phase == 0) {
            // attention epilogue: att[e,h] = mu[h]/4 * sum_o Q[e,h,o]*(acc+bias)
            float hsum[4][2][2];
#pragma unroll
            for (int mt = 0; mt < 4; mt++)
#pragma unroll
                for (int rf = 0; rf < 2; rf++)
#pragma unroll
                    for (int hl = 0; hl < 2; hl++) hsum[mt][rf][hl] = 0.f;
#pragma unroll
            for (int mt = 0; mt < 4; mt++) {
#pragma unroll
                for (int nt = 0; nt < 4; nt++) {
                    int col = C0 + nt * 8 + q4 * 2;
                    float b0 = sBa[col], b1 = sBa[col + 1];
                    int hl = nt >> 1;
                    hsum[mt][0][hl] += (acc[mt][nt][0] + b0) * qv1[mt][nt].x +
                                       (acc[mt][nt][1] + b1) * qv1[mt][nt].y;
                    hsum[mt][1][hl] += (acc[mt][nt][2] + b0) * qv2[mt][nt].x +
                                       (acc[mt][nt][3] + b1) * qv2[mt][nt].y;
                }
            }
#pragma unroll
            for (int mt = 0; mt < 4; mt++)
#pragma unroll
                for (int rf = 0; rf < 2; rf++)
#pragma unroll
                    for (int hl = 0; hl < 2; hl++) {
                        float v = hsum[mt][rf][hl];
                        v += __shfl_xor_sync(0xffffffffu, v, 1);
                        v += __shfl_xor_sync(0xffffffffu, v, 2);
                        if (q4 == 0) {
                            int p = rf ? pr2[mt] : pr1[mt];
                            if (p >= 0) {
                                int h = wc * 2 + hl;
                                out[(size_t)p * 8 + h] = v * sMu[h] * 0.25f;
                            }
                        }
                    }
        } else {
            // message epilogue
            float* mout = out + (size_t)E_EDGES * 8;
#pragma unroll
            for (int mt = 0; mt < 4; mt++) {
                int p1 = pr1[mt], p2 = pr2[mt];
#pragma unroll
                for (int nt = 0; nt < 4; nt++) {
                    int col = C0 + nt * 8 + q4 * 2;
                    float b0 = sBm[col], b1 = sBm[col + 1];
                    if (p1 >= 0)
                        *(float2*)(mout + (size_t)p1 * 128 + col) =
                            make_float2(acc[mt][nt][0] + b0, acc[mt][nt][1] + b1);
                    if (p2 >= 0)
                        *(float2*)(mout + (size_t)p2 * 128 + col) =
                            make_float2(acc[mt][nt][2] + b0, acc[mt][nt][3] + b1);
                }
            }
        }
    }
}

// ---------------- launch ----------------
extern "C" void kernel_launch(void* const* d_in, const int* in_sizes, int n_in,
                              void* d_out, int out_size) {
    const int*   etype = (const int*)d_in[0];
    const int*   tau   = (const int*)d_in[1];
    const float* h_s   = (const float*)d_in[2];
    const float* Q_t   = (const float*)d_in[3];
    const int*   dtv   = (const int*)d_in[4];
    const float* emb   = (const float*)d_in[5];
    const float* linW  = (const float*)d_in[6];
    const float* linb  = (const float*)d_in[7];
    const float* K_W   = (const float*)d_in[8];
    const float* K_b   = (const float*)d_in[9];
    const float* V_W   = (const float*)d_in[10];
    const float* V_b   = (const float*)d_in[11];
    const float* Watt  = (const float*)d_in[12];
    const float* Wmsg  = (const float*)d_in[13];
    const float* mu    = (const float*)d_in[14];
    float* out = (float*)d_out;

    cudaFuncSetAttribute(k_main, cudaFuncAttributeMaxDynamicSharedMemorySize, DYN_SMEM);

    k_rte<<<ML, INS>>>(emb, linW, linb);                 // also zeros g_counts
    k_hist<<<E_EDGES / 256, 256>>>(etype, tau);
    k_offsets<<<1, 128>>>();
    k_scatter<<<E_EDGES / 256, 256>>>(etype, tau);
    k_wcomb<<<dim3(OUTS, NG, 2), INS>>>(K_W, K_b, V_W, V_b, Watt, Wmsg);
    k_main<<<MAXBLK, 256, DYN_SMEM>>>(h_s, Q_t, dtv, mu, out);
}

// round 5
// speedup vs baseline: 5.2821x; 1.1763x over previous
#include <cuda_runtime.h>
#include <cuda_fp16.h>
#include <cstdint>

#define E_EDGES 131072
#define INS 128
#define OUTS 128
#define NH 8
#define DK 16
#define NG 32          /* tau(4) x etype(8) combined groups */
#define ML 240
#define TILE 128
#define MAXBLK (E_EDGES / TILE + NG)   /* 1056 */

// ---------------- device scratch ----------------
__device__ int   g_perm[MAXBLK * TILE];
__device__ int   g_counts[NG];
__device__ int   g_cursor[NG];
__device__ int   g_blk_info[MAXBLK];   // g | (valid<<8), or -1
__device__ float g_rte[ML * INS];
// combined weights [g][n][k] row-major fp16
__device__ __half g_Batt[NG * 16384];
__device__ __half g_Bmsg[NG * 16384];
__device__ float g_bias_att[NG * OUTS];
__device__ float g_bias_msg[NG * OUTS];

// ---------------- helpers ----------------
__device__ __forceinline__ uint32_t smem_u32(const void* p) {
    uint32_t a;
    asm("{ .reg .u64 t; cvta.to.shared.u64 t, %1; cvt.u32.u64 %0, t; }"
        : "=r"(a) : "l"(p));
    return a;
}
__device__ __forceinline__ void ldmx4(uint32_t* r, uint32_t addr) {
    asm volatile("ldmatrix.sync.aligned.m8n8.x4.shared.b16 {%0,%1,%2,%3}, [%4];"
                 : "=r"(r[0]), "=r"(r[1]), "=r"(r[2]), "=r"(r[3]) : "r"(addr));
}
__device__ __forceinline__ void ldmx2(uint32_t* r, uint32_t addr) {
    asm volatile("ldmatrix.sync.aligned.m8n8.x2.shared.b16 {%0,%1}, [%2];"
                 : "=r"(r[0]), "=r"(r[1]) : "r"(addr));
}
__device__ __forceinline__ void mma16816(float* c, const uint32_t* a, const uint32_t* b) {
    asm volatile(
        "mma.sync.aligned.m16n8k16.row.col.f32.f16.f16.f32 "
        "{%0,%1,%2,%3}, {%4,%5,%6,%7}, {%8,%9}, {%0,%1,%2,%3};"
        : "+f"(c[0]), "+f"(c[1]), "+f"(c[2]), "+f"(c[3])
        : "r"(a[0]), "r"(a[1]), "r"(a[2]), "r"(a[3]), "r"(b[0]), "r"(b[1]));
}
__device__ __forceinline__ void cp_async16(uint32_t saddr, const void* gaddr) {
    asm volatile("cp.async.cg.shared.global [%0], [%1], 16;"
                 :: "r"(saddr), "l"(gaddr));
}
__device__ __forceinline__ void cp_async_commit_wait() {
    asm volatile("cp.async.commit_group;");
    asm volatile("cp.async.wait_group 0;");
}

// ---------------- setup kernels ----------------
__global__ void k_rte(const float* __restrict__ emb,
                      const float* __restrict__ linW,
                      const float* __restrict__ linb) {
    __shared__ float se[INS];
    int d = blockIdx.x, o = threadIdx.x;
    if (d == 0 && o < NG) g_counts[o] = 0;
    se[o] = emb[d * INS + o];
    __syncthreads();
    float acc = linb[o];
    const float* w = linW + o * INS;
#pragma unroll 8
    for (int i = 0; i < INS; i++) acc += se[i] * w[i];
    g_rte[d * INS + o] = acc;
}

__global__ void k_hist(const int* __restrict__ etype, const int* __restrict__ tau) {
    __shared__ int sc[NG];
    if (threadIdx.x < NG) sc[threadIdx.x] = 0;
    __syncthreads();
    int i = blockIdx.x * blockDim.x + threadIdx.x;
    atomicAdd(&sc[tau[i] * 8 + etype[i]], 1);
    __syncthreads();
    if (threadIdx.x < NG && sc[threadIdx.x] > 0)
        atomicAdd(&g_counts[threadIdx.x], sc[threadIdx.x]);
}

__global__ void k_offsets() {
    __shared__ int seg[NG + 1];
    __shared__ int cnt[NG];
    if (threadIdx.x == 0) {
        int blk = 0;
        for (int g = 0; g < NG; g++) {
            seg[g] = blk;
            int c = g_counts[g];
            cnt[g] = c;
            g_cursor[g] = blk * TILE;
            blk += (c + TILE - 1) / TILE;
        }
        seg[NG] = blk;
    }
    __syncthreads();
    int total = seg[NG];
    for (int b = threadIdx.x; b < MAXBLK; b += blockDim.x) {
        int info = -1;
        if (b < total) {
            int g = 0;
            for (int q = 1; q < NG; q++)
                if (b >= seg[q]) g = q;
            int rem = cnt[g] - (b - seg[g]) * TILE;
            int valid = rem < TILE ? rem : TILE;
            info = g | (valid << 8);
        }
        g_blk_info[b] = info;
    }
}

__global__ void k_scatter(const int* __restrict__ etype, const int* __restrict__ tau) {
    __shared__ int lcount[NG];
    __shared__ int lbase[NG];
    int tid = threadIdx.x;
    if (tid < NG) lcount[tid] = 0;
    __syncthreads();
    int i = blockIdx.x * blockDim.x + tid;
    int g = tau[i] * 8 + etype[i];
    int rank = atomicAdd(&lcount[g], 1);
    __syncthreads();
    if (tid < NG && lcount[tid] > 0)
        lbase[tid] = atomicAdd(&g_cursor[tid], lcount[tid]);
    __syncthreads();
    g_perm[lbase[g] + rank] = i;
}

// combined weights Wc[g][n=h*16+o][i] = sum_k W2[et][o][k]*W1[t][h*16+k][i], fp16
__global__ void k_wcomb(const float* __restrict__ K_W, const float* __restrict__ K_b,
                        const float* __restrict__ V_W, const float* __restrict__ V_b,
                        const float* __restrict__ Watt, const float* __restrict__ Wmsg) {
    int n = blockIdx.x;        // 0..127
    int g = blockIdx.y;        // 0..31
    int which = blockIdx.z;    // 0 = att, 1 = msg
    int i = threadIdx.x;       // 0..127
    int t = g >> 3, et = g & 7, h = n >> 4, o = n & 15;
    const float* W2 = (which ? Wmsg : Watt) + (et * 16 + o) * 16;
    const float* W1 = (which ? V_W : K_W) + t * 16384;
    const float* b1 = (which ? V_b : K_b) + t * 128;
    float acc = 0.f, bacc = 0.f;
#pragma unroll
    for (int k = 0; k < 16; k++) {
        float w = W2[k];
        acc += w * W1[(h * 16 + k) * 128 + i];
        bacc += w * b1[h * 16 + k];
    }
    if (i == 0) (which ? g_bias_msg : g_bias_att)[g * 128 + n] = bacc;
    (which ? g_Bmsg : g_Batt)[g * 16384 + n * 128 + i] = __float2half_rn(acc);
}

// ---------------- main kernel ----------------
#define TILE_B  (TILE * 272)           /* 34816 bytes per padded tile */
#define SM_A    0
#define SM_BATT TILE_B
#define SM_BMSG (2 * TILE_B)
#define DYN_SMEM (3 * TILE_B)          /* 104448 */

__global__ __launch_bounds__(256, 2) void k_main(
    const float* __restrict__ h_s, const float* __restrict__ Q_t,
    const int* __restrict__ dtv, const float* __restrict__ mu,
    float* __restrict__ out) {
    extern __shared__ char dyn[];
    __shared__ int   sm_perm[TILE];
    __shared__ float sBa[OUTS];
    __shared__ float sBm[OUTS];
    __shared__ float sMu[NH];

    int b = blockIdx.x;
    int info = g_blk_info[b];
    if (info < 0) return;
    int g = info & 31;
    int valid = info >> 8;

    int tid = threadIdx.x;
    int lane = tid & 31;
    int w = tid >> 5;
    int wr = w >> 2, wc = w & 3;
    int R0 = wr * 64, C0 = wc * 32;
    uint32_t sb = smem_u32(dyn);

    // ---- 1) weight tiles via cp.async (latency hidden behind A build)
    {
        const uint4* s0 = (const uint4*)(g_Batt + g * 16384);
        const uint4* s1 = (const uint4*)(g_Bmsg + g * 16384);
#pragma unroll
        for (int it = 0; it < 8; it++) {
            int idx = tid + it * 256;
            int n = idx >> 4, kc = idx & 15;
            uint32_t off = (uint32_t)(n * 272 + kc * 16);
            cp_async16(sb + SM_BATT + off, s0 + idx);
            cp_async16(sb + SM_BMSG + off, s1 + idx);
        }
    }

    // ---- 2) per-block constants
    if (tid < TILE) {
        sm_perm[tid] = (tid < valid) ? g_perm[b * TILE + tid] : -1;
        sBa[tid] = g_bias_att[g * 128 + tid];
        sBm[tid] = g_bias_msg[g * 128 + tid];
    }
    if (tid < NH) sMu[tid] = mu[(g & 7) * NH + tid];

    // ---- 3) build A tile (fp16), 2 threads per row
    {
        int r = tid >> 1, half = tid & 1;
        int p = (r < valid) ? g_perm[b * TILE + r] : -1;
        const float4* hs4 = (const float4*)(h_s + (size_t)(p < 0 ? 0 : p) * 128);
        int d = (p >= 0) ? dtv[p] : 0;
        const float4* rt4 = (const float4*)(g_rte + d * 128);
        char* smA = dyn + SM_A + r * 272 + half * 128;
#pragma unroll 4
        for (int j = 0; j < 16; j++) {
            float v0 = 0.f, v1 = 0.f, v2 = 0.f, v3 = 0.f;
            if (p >= 0) {
                float4 hv = hs4[half * 16 + j];
                float4 rv = rt4[half * 16 + j];
                v0 = hv.x + rv.x; v1 = hv.y + rv.y;
                v2 = hv.z + rv.z; v3 = hv.w + rv.w;
            }
            __half2 h01 = __floats2half2_rn(v0, v1);
            __half2 h23 = __floats2half2_rn(v2, v3);
            uint2 pk;
            pk.x = *reinterpret_cast<unsigned*>(&h01);
            pk.y = *reinterpret_cast<unsigned*>(&h23);
            *(uint2*)(smA + j * 8) = pk;
        }
    }
    cp_async_commit_wait();
    __syncthreads();

    uint32_t aB = sb + SM_A;
    uint32_t aOff = (uint32_t)((R0 + (lane & 15)) * 272 + (lane >> 4) * 16);
    uint32_t bOff = (uint32_t)((C0 + (lane & 7)) * 272 + ((lane >> 3) & 1) * 16);
    int q4 = lane & 3, rquad = lane >> 2;

    int pr1[4], pr2[4];
#pragma unroll
    for (int mt = 0; mt < 4; mt++) {
        pr1[mt] = sm_perm[R0 + mt * 16 + rquad];
        pr2[mt] = sm_perm[R0 + mt * 16 + rquad + 8];
    }

#pragma unroll
    for (int phase = 0; phase < 2; phase++) {
        uint32_t bB = sb + (phase ? SM_BMSG : SM_BATT);
        float acc[4][4][4];
#pragma unroll
        for (int mt = 0; mt < 4; mt++)
#pragma unroll
            for (int nt = 0; nt < 4; nt++)
#pragma unroll
                for (int v = 0; v < 4; v++) acc[mt][nt][v] = 0.f;

#pragma unroll
        for (int k = 0; k < 8; k++) {
            uint32_t kb = (uint32_t)(k * 32);
            uint32_t bf[4][2];
#pragma unroll
            for (int nt = 0; nt < 4; nt++)
                ldmx2(bf[nt], bB + bOff + nt * 8 * 272 + kb);
#pragma unroll
            for (int mt = 0; mt < 4; mt++) {
                uint32_t af[4];
                ldmx4(af, aB + aOff + mt * 16 * 272 + kb);
#pragma unroll
                for (int nt = 0; nt < 4; nt++)
                    mma16816(acc[mt][nt], af, bf[nt]);
            }
        }

        if (phase == 0) {
            // attention epilogue: att[e,h] = mu[h]/4 * sum_o Q[e,h,o]*(acc+bias)
            float hsum[4][2][2];
#pragma unroll
            for (int mt = 0; mt < 4; mt++)
#pragma unroll
                for (int rf = 0; rf < 2; rf++)
#pragma unroll
                    for (int hl = 0; hl < 2; hl++) hsum[mt][rf][hl] = 0.f;
#pragma unroll
            for (int mt = 0; mt < 4; mt++) {
                const float* q1base = Q_t + (size_t)(pr1[mt] < 0 ? 0 : pr1[mt]) * 128;
                const float* q2base = Q_t + (size_t)(pr2[mt] < 0 ? 0 : pr2[mt]) * 128;
#pragma unroll
                for (int nt = 0; nt < 4; nt++) {
                    int col = C0 + nt * 8 + q4 * 2;
                    float b0 = sBa[col], b1 = sBa[col + 1];
                    int hl = nt >> 1;
                    float2 q1 = __ldg((const float2*)(q1base + col));
                    float2 q2 = __ldg((const float2*)(q2base + col));
                    hsum[mt][0][hl] += (acc[mt][nt][0] + b0) * q1.x +
                                       (acc[mt][nt][1] + b1) * q1.y;
                    hsum[mt][1][hl] += (acc[mt][nt][2] + b0) * q2.x +
                                       (acc[mt][nt][3] + b1) * q2.y;
                }
            }
#pragma unroll
            for (int mt = 0; mt < 4; mt++)
#pragma unroll
                for (int rf = 0; rf < 2; rf++)
#pragma unroll
                    for (int hl = 0; hl < 2; hl++) {
                        float v = hsum[mt][rf][hl];
                        v += __shfl_xor_sync(0xffffffffu, v, 1);
                        v += __shfl_xor_sync(0xffffffffu, v, 2);
                        if (q4 == 0) {
                            int p = rf ? pr2[mt] : pr1[mt];
                            if (p >= 0) {
                                int h = wc * 2 + hl;
                                out[(size_t)p * 8 + h] = v * sMu[h] * 0.25f;
                            }
                        }
                    }
        } else {
            // message epilogue
            float* mout = out + (size_t)E_EDGES * 8;
#pragma unroll
            for (int mt = 0; mt < 4; mt++) {
                int p1 = pr1[mt], p2 = pr2[mt];
#pragma unroll
                for (int nt = 0; nt < 4; nt++) {
                    int col = C0 + nt * 8 + q4 * 2;
                    float b0 = sBm[col], b1 = sBm[col + 1];
                    if (p1 >= 0)
                        *(float2*)(mout + (size_t)p1 * 128 + col) =
                            make_float2(acc[mt][nt][0] + b0, acc[mt][nt][1] + b1);
                    if (p2 >= 0)
                        *(float2*)(mout + (size_t)p2 * 128 + col) =
                            make_float2(acc[mt][nt][2] + b0, acc[mt][nt][3] + b1);
                }
            }
        }
    }
}

// ---------------- launch ----------------
extern "C" void kernel_launch(void* const* d_in, const int* in_sizes, int n_in,
                              void* d_out, int out_size) {
    const int*   etype = (const int*)d_in[0];
    const int*   tau   = (const int*)d_in[1];
    const float* h_s   = (const float*)d_in[2];
    const float* Q_t   = (const float*)d_in[3];
    const int*   dtv   = (const int*)d_in[4];
    const float* emb   = (const float*)d_in[5];
    const float* linW  = (const float*)d_in[6];
    const float* linb  = (const float*)d_in[7];
    const float* K_W   = (const float*)d_in[8];
    const float* K_b   = (const float*)d_in[9];
    const float* V_W   = (const float*)d_in[10];
    const float* V_b   = (const float*)d_in[11];
    const float* Watt  = (const float*)d_in[12];
    const float* Wmsg  = (const float*)d_in[13];
    const float* mu    = (const float*)d_in[14];
    float* out = (float*)d_out;

    cudaFuncSetAttribute(k_main, cudaFuncAttributeMaxDynamicSharedMemorySize, DYN_SMEM);

    k_rte<<<ML, INS>>>(emb, linW, linb);                 // also zeros g_counts
    k_hist<<<E_EDGES / 256, 256>>>(etype, tau);
    k_offsets<<<1, 128>>>();
    k_scatter<<<E_EDGES / 256, 256>>>(etype, tau);
    k_wcomb<<<dim3(OUTS, NG, 2), INS>>>(K_W, K_b, V_W, V_b, Watt, Wmsg);
    k_main<<<MAXBLK, 256, DYN_SMEM>>>(h_s, Q_t, dtv, mu, out);
}